// round 3
// baseline (speedup 1.0000x reference)
#include <cuda_runtime.h>
#include <math_constants.h>
#include <cstdint>

#define RR 512
#define CC 768
#define DD 256
#define HH 8
#define HD 32

#define SCALE_F 0.17677669529663687f   /* 1/sqrt(32) */

// Scratch: p[c][h][D] as float4 (768*8*64 float4 = 6.29 MB).
__device__ float4 g_p4[CC * HH * (DD / 4)];

// ---------------------------------------------------------------------------
// mbarrier helpers
// ---------------------------------------------------------------------------
__device__ __forceinline__ uint32_t smem_u32(const void* p) {
    uint32_t a;
    asm("{ .reg .u64 t; cvta.to.shared.u64 t, %1; cvt.u32.u64 %0, t; }" : "=r"(a) : "l"(p));
    return a;
}
__device__ __forceinline__ void mbar_init(uint32_t addr, uint32_t count) {
    asm volatile("mbarrier.init.shared.b64 [%0], %1;" :: "r"(addr), "r"(count) : "memory");
}
__device__ __forceinline__ void mbar_expect_tx(uint32_t addr, uint32_t bytes) {
    asm volatile("mbarrier.arrive.expect_tx.shared.b64 _, [%0], %1;" :: "r"(addr), "r"(bytes) : "memory");
}
__device__ __forceinline__ void mbar_arrive(uint32_t addr) {
    asm volatile("mbarrier.arrive.shared.b64 _, [%0];" :: "r"(addr) : "memory");
}
__device__ __forceinline__ void mbar_wait(uint32_t addr, uint32_t parity) {
    uint32_t done;
    asm volatile(
        "{\n\t.reg .pred p;\n\t"
        "mbarrier.try_wait.parity.acquire.cta.shared::cta.b64 p, [%1], %2;\n\t"
        "selp.b32 %0, 1, 0, p;\n\t}"
        : "=r"(done) : "r"(addr), "r"(parity) : "memory");
    if (!done) {
        asm volatile(
            "{\n\t.reg .pred P1;\n\t"
            "W_%=:\n\t"
            "mbarrier.try_wait.parity.acquire.cta.shared::cta.b64 P1, [%0], %1, 0x989680;\n\t"
            "@P1 bra.uni D_%=;\n\t"
            "bra.uni W_%=;\n\t"
            "D_%=:\n\t}"
            :: "r"(addr), "r"(parity) : "memory");
    }
}
__device__ __forceinline__ void bulk_cp_1d(uint32_t dst_smem, const void* src_gmem,
                                           uint32_t bytes, uint32_t mbar) {
    asm volatile(
        "cp.async.bulk.shared::cta.global.mbarrier::complete_tx::bytes [%0], [%1], %2, [%3];"
        :: "r"(dst_smem), "l"(src_gmem), "r"(bytes), "r"(mbar) : "memory");
}

// ---------------------------------------------------------------------------
// Kernel P: p[c,h,:] = (SCALE * (query[c] @ Wq.T))[h*32..+32) @ Wk[h*32..,:]
// Grid: 96 blocks x 8 columns, 256 threads. Wq staged via smem (coalesced).
// Dynamic smem layout:
//   q_s  [8*256]  floats  @ 0       (8 KB)
//   qf_s [8*256]  floats  @ 8192    (8 KB)
//   w_s  [64*260] floats  @ 16384   (66560 B)    row pad 260 -> conflict-free
// ---------------------------------------------------------------------------
#define P_SMEM_BYTES (16384 + 64 * 260 * 4)

__global__ __launch_bounds__(256) void kernelP(const float* __restrict__ msa,
                                               const float* __restrict__ Wq,
                                               const float* __restrict__ Wk) {
    extern __shared__ float psm[];
    float* q_s  = psm;
    float* qf_s = psm + 2048;
    float* w_s  = psm + 4096;

    const int t  = threadIdx.x;
    const int c0 = blockIdx.x * 8;

    // Load 8 query rows (contiguous 8 KB).
    {
        const float4* src = (const float4*)(msa + (size_t)c0 * DD);
        float4* dst = (float4*)q_s;
        for (int i = t; i < 8 * DD / 4; i += 256) dst[i] = src[i];
    }

    // Phase A: Qf[c][j] = SCALE * dot(q[c], Wq[j]) via smem-staged Wq j-tiles.
    const int j  = t & 63;
    const int cp = t >> 6;            // 0..3 -> columns (2*cp, 2*cp+1)
    for (int jt = 0; jt < 4; jt++) {
        __syncthreads();
        // Stage Wq rows [jt*64, jt*64+64): coalesced 64 KB.
        {
            const float4* src = (const float4*)(Wq + (size_t)jt * 64 * DD);
            for (int i = t; i < 64 * DD / 4; i += 256) {
                int row = i >> 6, c4 = i & 63;
                ((float4*)(w_s + row * 260))[c4] = src[i];
            }
        }
        __syncthreads();
        const float4* wrow = (const float4*)(w_s + j * 260);
        const float4* qa   = (const float4*)(q_s + (2 * cp) * DD);
        const float4* qb   = (const float4*)(q_s + (2 * cp + 1) * DD);
        float a0 = 0.f, a1 = 0.f;
#pragma unroll 8
        for (int i = 0; i < DD / 4; i++) {
            float4 w = wrow[i];
            float4 x = qa[i];
            float4 y = qb[i];
            a0 += w.x * x.x; a0 += w.y * x.y; a0 += w.z * x.z; a0 += w.w * x.w;
            a1 += w.x * y.x; a1 += w.y * y.y; a1 += w.z * y.z; a1 += w.w * y.w;
        }
        qf_s[(2 * cp) * DD + jt * 64 + j]     = a0 * SCALE_F;
        qf_s[(2 * cp + 1) * DD + jt * 64 + j] = a1 * SCALE_F;
    }
    __syncthreads();

    // Phase B: p[c][h][D] = sum_{d<32} Qf[c][h*32+d] * Wk[h*32+d][D]
    {
        const int d4 = t & 63;        // float4 index into D
        const int cg = t >> 6;
        const int cA = 2 * cg, cB = 2 * cg + 1;
        const float4* wk = (const float4*)Wk;
        for (int h = 0; h < HH; h++) {
            float4 a0 = make_float4(0.f, 0.f, 0.f, 0.f);
            float4 a1 = make_float4(0.f, 0.f, 0.f, 0.f);
#pragma unroll
            for (int d = 0; d < HD; d++) {
                float4 w = wk[(h * HD + d) * (DD / 4) + d4];   // coalesced
                float f0 = qf_s[cA * DD + h * HD + d];          // broadcast
                float f1 = qf_s[cB * DD + h * HD + d];
                a0.x += f0 * w.x; a0.y += f0 * w.y; a0.z += f0 * w.z; a0.w += f0 * w.w;
                a1.x += f1 * w.x; a1.y += f1 * w.y; a1.z += f1 * w.z; a1.w += f1 * w.w;
            }
            g_p4[((size_t)(c0 + cA) * HH + h) * (DD / 4) + d4] = a0;
            g_p4[((size_t)(c0 + cB) * HH + h) * (DD / 4) + d4] = a1;
        }
    }
}

// ---------------------------------------------------------------------------
// Kernel Main: one block per column c. MSA[:, c, :] streamed via a 4-stage
// cp.async.bulk + mbarrier pipeline (16 rows = 16 KB per stage), logits,
// masked softmax over r, output [r][c][h].
//
// Dynamic smem layout:
//   buf    @ 0       : 4 * 16 * 1024 B = 65536
//   logits @ 65536   : 512 * 9 * 4     = 18432
//   mask   @ 83968   : 512 * 4         = 2048
//   bars   @ 86016   : 8 * 8           = 64     (full[0..3], empty[0..3])
// ---------------------------------------------------------------------------
#define STAGES      4
#define STAGE_ROWS  16
#define STAGE_BYTES (STAGE_ROWS * 1024)
#define NSTAGE      (RR / STAGE_ROWS)          /* 32 */
#define MAIN_SMEM_BYTES (65536 + 18432 + 2048 + 64)

__global__ __launch_bounds__(256, 2) void kernelMain(const float* __restrict__ msa,
                                                     const int* __restrict__ mask,
                                                     float* __restrict__ out) {
    extern __shared__ float msm[];
    float* buf     = msm;                        // [4][16][256]
    float* logit_s = msm + 16384;                // [512][9]
    int*   mask_s  = (int*)(msm + 16384 + 4608);
    uint32_t bar0  = smem_u32(msm + 16384 + 4608 + 512);

    const int c    = blockIdx.x;
    const int t    = threadIdx.x;
    const int warp = t >> 5;
    const int lane = t & 31;

    // Issue mask LDGs as early as possible (independent of everything else).
    int mymask[2];
    mymask[0] = mask[t];
    mymask[1] = mask[256 + t];

    // Barrier init: full[k] count 1 (producer expect_tx), empty[k] count 8 (warps).
    if (t == 0) {
        for (int k = 0; k < STAGES; k++) {
            mbar_init(bar0 + k * 8, 1);              // full
            mbar_init(bar0 + 32 + k * 8, 8);         // empty
        }
    }
    __syncthreads();

    // Kick off the first STAGES stages immediately.
    if (t == 0) {
        for (int s = 0; s < STAGES; s++) {
            mbar_expect_tx(bar0 + s * 8, STAGE_BYTES);
            uint32_t dst = smem_u32(buf) + s * STAGE_BYTES;
#pragma unroll
            for (int row = 0; row < STAGE_ROWS; row++) {
                const float* src = msa + ((size_t)(s * STAGE_ROWS + row) * CC + c) * DD;
                bulk_cp_1d(dst + row * 1024, src, 1024, bar0 + s * 8);
            }
        }
    }

    mask_s[t]       = mymask[0];
    mask_s[256 + t] = mymask[1];

    // p[c] resident in registers.
    float4 pA[HH], pB[HH];
    {
        const float4* pg = g_p4 + (size_t)c * HH * (DD / 4);
#pragma unroll
        for (int h = 0; h < HH; h++) {
            pA[h] = pg[h * 64 + lane];
            pB[h] = pg[h * 64 + 32 + lane];
        }
    }

    const bool hi16 = (lane & 16) != 0;
    const bool hi8  = (lane & 8) != 0;
    const bool hi4  = (lane & 4) != 0;
    const int  hsel = (lane >> 2) & 7;

    // Pipelined main loop over 32 stages.
    for (int s = 0; s < NSTAGE; s++) {
        const int slot = s & (STAGES - 1);
        const uint32_t par = (s >> 2) & 1;
        mbar_wait(bar0 + slot * 8, par);                // wait full

        const float* stg = buf + slot * (STAGE_ROWS * 256);
#pragma unroll
        for (int jrow = 0; jrow < 2; jrow++) {
            const int rloc = warp * 2 + jrow;
            const int r    = s * STAGE_ROWS + rloc;
            const float4* row4 = (const float4*)(stg + rloc * 256);
            float4 mA = row4[lane];
            float4 mB = row4[32 + lane];

            float acc[HH];
#pragma unroll
            for (int h = 0; h < HH; h++) {
                float v;
                v  = mA.x * pA[h].x;
                v += mA.y * pA[h].y;
                v += mA.z * pA[h].z;
                v += mA.w * pA[h].w;
                v += mB.x * pB[h].x;
                v += mB.y * pB[h].y;
                v += mB.z * pB[h].z;
                v += mB.w * pB[h].w;
                acc[h] = v;
            }
            // Segmented butterfly: 8 partials x 32 lanes -> head totals.
            float k1[4];
#pragma unroll
            for (int q = 0; q < 4; q++) {
                float send = hi16 ? acc[q] : acc[q + 4];
                float recv = __shfl_xor_sync(0xffffffffu, send, 16);
                k1[q] = (hi16 ? acc[q + 4] : acc[q]) + recv;
            }
            float k2[2];
#pragma unroll
            for (int q = 0; q < 2; q++) {
                float send = hi8 ? k1[q] : k1[q + 2];
                float recv = __shfl_xor_sync(0xffffffffu, send, 8);
                k2[q] = (hi8 ? k1[q + 2] : k1[q]) + recv;
            }
            {
                float send = hi4 ? k2[0] : k2[1];
                float recv = __shfl_xor_sync(0xffffffffu, send, 4);
                float res  = (hi4 ? k2[1] : k2[0]) + recv;
                res += __shfl_xor_sync(0xffffffffu, res, 2);
                res += __shfl_xor_sync(0xffffffffu, res, 1);
                if ((lane & 3) == 0) logit_s[r * 9 + hsel] = res;
            }
        }

        __syncwarp();
        if (lane == 0) mbar_arrive(bar0 + 32 + slot * 8);    // empty arrive

        // Producer refills this slot for stage s+4.
        if (t == 0 && s + STAGES < NSTAGE) {
            mbar_wait(bar0 + 32 + slot * 8, par);            // all warps drained slot
            mbar_expect_tx(bar0 + slot * 8, STAGE_BYTES);
            uint32_t dst = smem_u32(buf) + slot * STAGE_BYTES;
            const int snew = s + STAGES;
#pragma unroll
            for (int row = 0; row < STAGE_ROWS; row++) {
                const float* src = msa + ((size_t)(snew * STAGE_ROWS + row) * CC + c) * DD;
                bulk_cp_1d(dst + row * 1024, src, 1024, bar0 + slot * 8);
            }
        }
    }
    __syncthreads();

    // Masked softmax over r: warp w owns head h = w.
    {
        const int h = warp;
        float vals[16];
        float mx = -CUDART_INF_F;
#pragma unroll
        for (int i = 0; i < 16; i++) {
            const int r = i * 32 + lane;
            float v = logit_s[r * 9 + h];
            vals[i] = v;
            if (mask_s[r] != 0) mx = fmaxf(mx, v);
        }
#pragma unroll
        for (int o = 16; o > 0; o >>= 1)
            mx = fmaxf(mx, __shfl_xor_sync(0xffffffffu, mx, o));

        if (mx > -CUDART_INF_F) {
            float sum = 0.f;
#pragma unroll
            for (int i = 0; i < 16; i++) {
                const int r = i * 32 + lane;
                float e = (mask_s[r] != 0) ? __expf(vals[i] - mx) : 0.f;
                vals[i] = e;
                sum += e;
            }
#pragma unroll
            for (int o = 16; o > 0; o >>= 1)
                sum += __shfl_xor_sync(0xffffffffu, sum, o);
            const float inv = 1.f / sum;
#pragma unroll
            for (int i = 0; i < 16; i++) {
                const int r = i * 32 + lane;
                logit_s[r * 9 + h] = vals[i] * inv;
            }
        } else {
            const float u = 1.0f / (float)RR;   // all-masked: uniform (matches jax)
#pragma unroll
            for (int i = 0; i < 16; i++) {
                const int r = i * 32 + lane;
                logit_s[r * 9 + h] = u;
            }
        }
    }
    __syncthreads();

    // Output: 8-lane groups write 32B contiguous sectors.
    {
        const int h  = t & 7;
        const int r0 = t >> 3;
#pragma unroll
        for (int i = 0; i < 16; i++) {
            const int r = i * 32 + r0;
            out[((size_t)r * CC + c) * HH + h] = logit_s[r * 9 + h];
        }
    }
}

// ---------------------------------------------------------------------------
extern "C" void kernel_launch(void* const* d_in, const int* in_sizes, int n_in,
                              void* d_out, int out_size) {
    const float* msa  = (const float*)d_in[0];   // MSA_emb (1,512,768,256) f32
    const int*   mask = (const int*)d_in[1];     // seq_mask (1,512) i32
    const float* Wq   = (const float*)d_in[2];   // (256,256) f32
    const float* Wk   = (const float*)d_in[3];   // (256,256) f32
    float* out = (float*)d_out;                  // (1,512,768,8,1) f32

    cudaFuncSetAttribute(kernelP, cudaFuncAttributeMaxDynamicSharedMemorySize,
                         P_SMEM_BYTES);
    cudaFuncSetAttribute(kernelMain, cudaFuncAttributeMaxDynamicSharedMemorySize,
                         MAIN_SMEM_BYTES);

    kernelP<<<CC / 8, 256, P_SMEM_BYTES>>>(msa, Wq, Wk);
    kernelMain<<<CC, 256, MAIN_SMEM_BYTES>>>(msa, mask, out);
}